// round 14
// baseline (speedup 1.0000x reference)
#include <cuda_runtime.h>
#include <cuda_fp16.h>
#include <math.h>
#include <stdint.h>

#define H_DIM 1024
#define F_DIM 4096
#define E_NUM 8
#define T_MAX 4096

#define BM 128
#define BN 128
#define BK 32
#define APITCH 80
#define BPITCH 544
#define ABYTES (BM * APITCH)      // 10240
#define BBYTES (16 * BPITCH)      // 8704
#define BUFB   (ABYTES + BBYTES)  // 18944
#define NSTAGE 5
#define SMEM_DYN (NSTAGE * BUFB)  // 94720

// ---------------- device scratch (accessed ONLY from device code) ----------------
__device__ int   g_counts[E_NUM];
__device__ int   g_tok[E_NUM * T_MAX];
__device__ float g_gate[T_MAX * 2];
__device__ int   g_slot[T_MAX * 2];
__device__ __align__(16) __half g_xh [(size_t)T_MAX * H_DIM];
__device__ __align__(16) __half g_w1i[(size_t)E_NUM * H_DIM * F_DIM];
__device__ __align__(16) __half g_w2i[(size_t)E_NUM * F_DIM * H_DIM];
__device__ __align__(16) __half g_h  [(size_t)E_NUM * T_MAX * F_DIM];
__device__ __align__(16) float  g_y2 [(size_t)E_NUM * T_MAX * H_DIM];

#define MMA_F16(c, a, b0, b1) \
    asm volatile("mma.sync.aligned.m16n8k16.row.col.f32.f16.f16.f32 " \
        "{%0,%1,%2,%3}, {%4,%5,%6,%7}, {%8,%9}, {%0,%1,%2,%3};" \
        : "+f"((c)[0]),"+f"((c)[1]),"+f"((c)[2]),"+f"((c)[3]) \
        : "r"((a)[0]),"r"((a)[1]),"r"((a)[2]),"r"((a)[3]), "r"(b0),"r"(b1))

#define CP16(d, s) asm volatile("cp.async.cg.shared.global [%0], [%1], 16;" :: "r"(d), "l"(s))
#define CP_COMMIT  asm volatile("cp.async.commit_group;" ::: "memory")
#define CP_WAIT3   asm volatile("cp.async.wait_group 3;" ::: "memory")
#define LDSM4(r0,r1,r2,r3,addr) \
    asm volatile("ldmatrix.sync.aligned.m8n8.x4.shared.b16 {%0,%1,%2,%3}, [%4];" \
        : "=r"(r0),"=r"(r1),"=r"(r2),"=r"(r3) : "r"(addr))

__device__ __forceinline__ uint32_t smem_u32(const void* p) {
    uint32_t a;
    asm("{ .reg .u64 t; cvta.to.shared.u64 t, %1; cvt.u32.u64 %0, t; }" : "=r"(a) : "l"(p));
    return a;
}
__device__ __forceinline__ float gelu_f(float v) {
    return 0.5f * v * (1.0f + erff(v * 0.70710678118654752f));
}

// ---------------- reset ----------------
__global__ void reset_kernel() {
    if (threadIdx.x < E_NUM) g_counts[threadIdx.x] = 0;
}

// ---------------- router: warp-per-token, rw staged in smem (+ fused x->fp16) -------
__global__ __launch_bounds__(256)
void router_kernel(const float* __restrict__ x,
                   const float* __restrict__ rw, int T) {
    __shared__ float srw[H_DIM * 9];
    for (int idx = threadIdx.x; idx < H_DIM * E_NUM; idx += 256)
        srw[(idx >> 3) * 9 + (idx & 7)] = rw[idx];
    __syncthreads();

    int lane = threadIdx.x & 31;
    int t = blockIdx.x * 8 + (threadIdx.x >> 5);
    if (t >= T) return;
    const float* xt = x + (size_t)t * H_DIM;
    __half* xh = g_xh + (size_t)t * H_DIM;

    float acc[8] = {0.f, 0.f, 0.f, 0.f, 0.f, 0.f, 0.f, 0.f};
    #pragma unroll 4
    for (int i = lane; i < H_DIM; i += 32) {
        float v = xt[i];
        xh[i] = __float2half_rn(v);
        const float* r = srw + i * 9;
        #pragma unroll
        for (int e = 0; e < 8; e++)
            acc[e] = fmaf(v, r[e], acc[e]);
    }
    #pragma unroll
    for (int e = 0; e < 8; e++)
        #pragma unroll
        for (int o = 16; o; o >>= 1)
            acc[e] += __shfl_xor_sync(0xffffffffu, acc[e], o);

    if (lane == 0) {
        int i0 = 0; float v0 = acc[0];
        #pragma unroll
        for (int j = 1; j < 8; j++) if (acc[j] > v0) { v0 = acc[j]; i0 = j; }
        int i1 = -1; float v1 = -3.4e38f;
        #pragma unroll
        for (int j = 0; j < 8; j++)
            if (j != i0 && acc[j] > v1) { v1 = acc[j]; i1 = j; }
        float p0 = 1.f / (1.f + expf(-v0));
        float p1 = 1.f / (1.f + expf(-v1));
        int pos0 = atomicAdd(&g_counts[i0], 1);
        int pos1 = atomicAdd(&g_counts[i1], 1);
        g_tok[i0 * T_MAX + pos0] = t;
        g_tok[i1 * T_MAX + pos1] = t;
        g_gate[t * 2 + 0] = p0;  g_slot[t * 2 + 0] = i0 * T_MAX + pos0;
        g_gate[t * 2 + 1] = p1;  g_slot[t * 2 + 1] = i1 * T_MAX + pos1;
    }
}

// ---------------- weight interleave (R8 version) ----------------
template <bool FIRST>
__global__ void interleave_kernel(const float* __restrict__ w) {
    const int K = FIRST ? H_DIM : F_DIM;
    const int N = FIRST ? F_DIM : H_DIM;
    __half2* wi = (__half2*)(FIRST ? g_w1i : g_w2i);
    int n  = (blockIdx.x * 256 + threadIdx.x) * 4;
    int k2 = blockIdx.y;
    int e  = blockIdx.z;
    size_t eo = (size_t)e * K * N;
    float4 a = *(const float4*)(w + eo + (size_t)(2 * k2)     * N + n);
    float4 b = *(const float4*)(w + eo + (size_t)(2 * k2 + 1) * N + n);
    __half2 o[4];
    o[0] = __halves2half2(__float2half_rn(a.x), __float2half_rn(b.x));
    o[1] = __halves2half2(__float2half_rn(a.y), __float2half_rn(b.y));
    o[2] = __halves2half2(__float2half_rn(a.z), __float2half_rn(b.z));
    o[3] = __halves2half2(__float2half_rn(a.w), __float2half_rn(b.w));
    *(uint4*)(wi + ((size_t)e * (K / 2) + k2) * N + n) = *(const uint4*)o;
}

// ---------------- fp16 mma GEMM (R8 mainloop, 5-stage, expert-offset) ---------------
template <bool FIRST>
__global__ __launch_bounds__(256)
void gemm_f16(const float* __restrict__ bias, int e_base) {
    const int Kd = FIRST ? H_DIM : F_DIM;
    const int Nd = FIRST ? F_DIM : H_DIM;
    const __half* Ag = FIRST ? g_xh : g_h;
    const __half* Wi = FIRST ? g_w1i : g_w2i;

    int e = e_base + blockIdx.z;
    int n_e = g_counts[e];
    int row0 = blockIdx.y * BM;
    if (row0 >= n_e) return;
    int n0 = blockIdx.x * BN;
    int eT = e * T_MAX;

    extern __shared__ __align__(16) char sm[];
    uint32_t sbase = smem_u32(sm);
    int t = threadIdx.x, wid = t >> 5, l = t & 31;
    int q = l & 3, g = l >> 2;

    int ar = t >> 1, hf = t & 1;
    int gr = row0 + ar;
    int grc = (gr < n_e) ? gr : (n_e - 1);
    const __half* a_src;
    if (FIRST) {
        int tok = g_tok[eT + grc];
        a_src = Ag + (size_t)tok * Kd + hf * 16;
    } else {
        a_src = Ag + (size_t)(eT + grc) * Kd + hf * 16;
    }
    uint32_t a_sts = (uint32_t)(ar * APITCH + hf * 32);

    int br = t >> 4, bc = t & 15;
    const __half* b_src = Wi + (((size_t)e * (Kd / 2) + br) * Nd + n0 + bc * 8) * 2;
    uint32_t b_sts = (uint32_t)(ABYTES + br * BPITCH + bc * 32);
    const size_t bstep = (size_t)16 * Nd * 2;

    float c[4][4][4];
    #pragma unroll
    for (int i = 0; i < 4; i++)
        #pragma unroll
        for (int j = 0; j < 4; j++)
            #pragma unroll
            for (int r = 0; r < 4; r++) c[i][j][r] = 0.f;

    auto issue = [&](int it) {
        int s = it % NSTAGE;
        uint32_t ad = sbase + (uint32_t)s * BUFB + a_sts;
        uint32_t bd = sbase + (uint32_t)s * BUFB + b_sts;
        const char* asrc = (const char*)(a_src + (size_t)it * BK);
        const char* bsrc = (const char*)(b_src + (size_t)it * bstep);
        CP16(ad,      asrc);
        CP16(ad + 16, asrc + 16);
        CP16(bd,      bsrc);
        CP16(bd + 16, bsrc + 16);
    };

    int wm = (wid & 1) * 64, wn = (wid >> 1) * 32;
    const int NK = Kd / BK;

    uint32_t a_lm = (uint32_t)((l & 15) * APITCH + (l >> 4) * 16);

    issue(0); CP_COMMIT;
    issue(1); CP_COMMIT;
    issue(2); CP_COMMIT;
    issue(3); CP_COMMIT;

    for (int k = 0; k < NK; k++) {
        CP_WAIT3;
        __syncthreads();
        if (k + 4 < NK) issue(k + 4);
        CP_COMMIT;

        uint32_t sAu = sbase + (uint32_t)(k % NSTAGE) * BUFB;
        const char* sB = sm + (k % NSTAGE) * BUFB + ABYTES;

        #pragma unroll
        for (int ks = 0; ks < 2; ks++) {
            uint32_t af[4][4];
            #pragma unroll
            for (int mf = 0; mf < 4; mf++) {
                uint32_t addr = sAu + (uint32_t)((wm + mf * 16) * APITCH + ks * 32) + a_lm;
                LDSM4(af[mf][0], af[mf][1], af[mf][2], af[mf][3], addr);
            }
            #pragma unroll
            for (int nf = 0; nf < 4; nf++) {
                int n_loc = wn + nf * 8 + g;
                uint32_t b0 = *(const uint32_t*)(sB + (ks * 8 + q)     * BPITCH + n_loc * 4);
                uint32_t b1 = *(const uint32_t*)(sB + (ks * 8 + 4 + q) * BPITCH + n_loc * 4);
                #pragma unroll
                for (int mf = 0; mf < 4; mf++)
                    MMA_F16(c[mf][nf], af[mf], b0, b1);
            }
        }
    }

    // -------- epilogue --------
    const float* Bp = bias + (size_t)e * Nd;
    #pragma unroll
    for (int mf = 0; mf < 4; mf++) {
        #pragma unroll
        for (int half = 0; half < 2; half++) {
            int rr = row0 + wm + mf * 16 + g + half * 8;
            if (rr >= n_e) continue;
            size_t rowoff = (size_t)(eT + rr) * Nd;
            #pragma unroll
            for (int nf = 0; nf < 4; nf++) {
                int cc = n0 + wn + nf * 8 + q * 2;
                float v0 = c[mf][nf][half * 2 + 0] + __ldg(Bp + cc);
                float v1 = c[mf][nf][half * 2 + 1] + __ldg(Bp + cc + 1);
                if (FIRST) {
                    v0 = gelu_f(v0);
                    v1 = gelu_f(v1);
                    *(__half2*)(g_h + rowoff + cc) =
                        __halves2half2(__float2half_rn(v0), __float2half_rn(v1));
                } else {
                    *(float2*)(g_y2 + rowoff + cc) = make_float2(v0, v1);
                }
            }
        }
    }
}

// ---------------- combine ----------------
__global__ void combine_kernel(float* __restrict__ out, int T) {
    int idx = blockIdx.x * blockDim.x + threadIdx.x;
    int total = T * (H_DIM / 4);
    if (idx >= total) return;
    int t = idx / (H_DIM / 4);
    int j = (idx % (H_DIM / 4)) * 4;
    float g0 = g_gate[t * 2 + 0], g1 = g_gate[t * 2 + 1];
    int   s0 = g_slot[t * 2 + 0], s1 = g_slot[t * 2 + 1];
    float4 a = *(const float4*)&g_y2[(size_t)s0 * H_DIM + j];
    float4 b = *(const float4*)&g_y2[(size_t)s1 * H_DIM + j];
    float4 o;
    o.x = fmaf(g0, a.x, g1 * b.x);
    o.y = fmaf(g0, a.y, g1 * b.y);
    o.z = fmaf(g0, a.z, g1 * b.z);
    o.w = fmaf(g0, a.w, g1 * b.w);
    *(float4*)(out + (size_t)t * H_DIM + j) = o;
}

// ---------------- launch: forked interleaves + expert-halved GEMM pipeline ---------
extern "C" void kernel_launch(void* const* d_in, const int* in_sizes, int n_in,
                              void* d_out, int out_size) {
    const float* x  = (const float*)d_in[0];
    const float* rw = (const float*)d_in[1];
    const float* w1 = (const float*)d_in[2];
    const float* b1 = (const float*)d_in[3];
    const float* w2 = (const float*)d_in[4];
    const float* b2 = (const float*)d_in[5];
    float* out = (float*)d_out;
    int T = in_sizes[0] / H_DIM;

    static cudaStream_t s1;
    static cudaEvent_t evStart, evI1, evA, evC, evD;
    static int init = 0;
    if (!init) {
        cudaFuncSetAttribute(gemm_f16<true>,  cudaFuncAttributeMaxDynamicSharedMemorySize, SMEM_DYN);
        cudaFuncSetAttribute(gemm_f16<false>, cudaFuncAttributeMaxDynamicSharedMemorySize, SMEM_DYN);
        cudaStreamCreateWithFlags(&s1, cudaStreamNonBlocking);
        cudaEventCreateWithFlags(&evStart, cudaEventDisableTiming);
        cudaEventCreateWithFlags(&evI1,    cudaEventDisableTiming);
        cudaEventCreateWithFlags(&evA,     cudaEventDisableTiming);
        cudaEventCreateWithFlags(&evC,     cudaEventDisableTiming);
        cudaEventCreateWithFlags(&evD,     cudaEventDisableTiming);
        init = 1;
    }

    // fork: side stream does the weight interleaves
    cudaEventRecord(evStart, 0);
    cudaStreamWaitEvent(s1, evStart, 0);
    interleave_kernel<true ><<<dim3(F_DIM / 1024, H_DIM / 2, E_NUM), 256, 0, s1>>>(w1);
    cudaEventRecord(evI1, s1);
    interleave_kernel<false><<<dim3(H_DIM / 1024, F_DIM / 2, E_NUM), 256, 0, s1>>>(w2);
    // s1 is now ordered after both interleaves; G2 launches below inherit that.

    // main: routing (+x2h) in parallel with interleaves
    reset_kernel<<<1, 32>>>();
    router_kernel<<<(T + 7) / 8, 256>>>(x, rw, T);

    dim3 g1(F_DIM / BN, (T + BM - 1) / BM, 4);
    dim3 g2(H_DIM / BN, (T + BM - 1) / BM, 4);

    cudaStreamWaitEvent(0, evI1, 0);
    gemm_f16<true><<<g1, 256, SMEM_DYN>>>(b1, 0);     // G1a: experts 0-3
    cudaEventRecord(evA, 0);
    gemm_f16<true><<<g1, 256, SMEM_DYN>>>(b1, 4);     // G1b: experts 4-7
    cudaEventRecord(evC, 0);

    cudaStreamWaitEvent(s1, evA, 0);
    gemm_f16<false><<<g2, 256, SMEM_DYN, s1>>>(b2, 0); // G2a overlaps G1b
    cudaStreamWaitEvent(s1, evC, 0);
    gemm_f16<false><<<g2, 256, SMEM_DYN, s1>>>(b2, 4); // G2b
    cudaEventRecord(evD, s1);

    cudaStreamWaitEvent(0, evD, 0);
    int total = T * (H_DIM / 4);
    combine_kernel<<<(total + 255) / 256, 256>>>(out, T);
}

// round 15
// speedup vs baseline: 1.0286x; 1.0286x over previous
#include <cuda_runtime.h>
#include <cuda_fp16.h>
#include <math.h>
#include <stdint.h>

#define H_DIM 1024
#define F_DIM 4096
#define E_NUM 8
#define T_MAX 4096

#define BM 128
#define BN 128
#define BK 32
#define APITCH 80
#define BPITCH 544
#define ABYTES (BM * APITCH)      // 10240
#define BBYTES (16 * BPITCH)      // 8704
#define BUFB   (ABYTES + BBYTES)  // 18944
#define NSTAGE 4
#define SMEM_DYN (NSTAGE * BUFB)  // 75776

// ---------------- device scratch (accessed ONLY from device code) ----------------
__device__ int   g_counts[E_NUM];
__device__ int   g_tok[E_NUM * T_MAX];
__device__ float g_rowgate[E_NUM * T_MAX];      // gate per (expert, slot)
__device__ __align__(16) __half g_xh [(size_t)T_MAX * H_DIM];
__device__ __align__(16) __half g_w1i[(size_t)E_NUM * H_DIM * F_DIM];
__device__ __align__(16) __half g_w2i[(size_t)E_NUM * F_DIM * H_DIM];
__device__ __align__(16) __half g_h  [(size_t)E_NUM * T_MAX * F_DIM];

#define MMA_F16(c, a, b0, b1) \
    asm volatile("mma.sync.aligned.m16n8k16.row.col.f32.f16.f16.f32 " \
        "{%0,%1,%2,%3}, {%4,%5,%6,%7}, {%8,%9}, {%0,%1,%2,%3};" \
        : "+f"((c)[0]),"+f"((c)[1]),"+f"((c)[2]),"+f"((c)[3]) \
        : "r"((a)[0]),"r"((a)[1]),"r"((a)[2]),"r"((a)[3]), "r"(b0),"r"(b1))

#define CP16(d, s) asm volatile("cp.async.cg.shared.global [%0], [%1], 16;" :: "r"(d), "l"(s))
#define CP_COMMIT  asm volatile("cp.async.commit_group;" ::: "memory")
#define CP_WAIT2   asm volatile("cp.async.wait_group 2;" ::: "memory")
#define LDSM4(r0,r1,r2,r3,addr) \
    asm volatile("ldmatrix.sync.aligned.m8n8.x4.shared.b16 {%0,%1,%2,%3}, [%4];" \
        : "=r"(r0),"=r"(r1),"=r"(r2),"=r"(r3) : "r"(addr))

__device__ __forceinline__ uint32_t smem_u32(const void* p) {
    uint32_t a;
    asm("{ .reg .u64 t; cvta.to.shared.u64 t, %1; cvt.u32.u64 %0, t; }" : "=r"(a) : "l"(p));
    return a;
}
__device__ __forceinline__ float gelu_f(float v) {
    return 0.5f * v * (1.0f + erff(v * 0.70710678118654752f));
}

// ---------------- reset ----------------
__global__ void reset_kernel() {
    if (threadIdx.x < E_NUM) g_counts[threadIdx.x] = 0;
}

// ---------------- zero output (out gets exactly 2 atomic adds per element) ---------
__global__ void zero_out_kernel(float* __restrict__ out, int n4) {
    int i = blockIdx.x * blockDim.x + threadIdx.x;
    if (i < n4) ((float4*)out)[i] = make_float4(0.f, 0.f, 0.f, 0.f);
}

// ---------------- router: warp-per-token, rw staged in smem (+ fused x->fp16) -------
__global__ __launch_bounds__(256)
void router_kernel(const float* __restrict__ x,
                   const float* __restrict__ rw, int T) {
    __shared__ float srw[H_DIM * 9];
    for (int idx = threadIdx.x; idx < H_DIM * E_NUM; idx += 256)
        srw[(idx >> 3) * 9 + (idx & 7)] = rw[idx];
    __syncthreads();

    int lane = threadIdx.x & 31;
    int t = blockIdx.x * 8 + (threadIdx.x >> 5);
    if (t >= T) return;
    const float* xt = x + (size_t)t * H_DIM;
    __half* xh = g_xh + (size_t)t * H_DIM;

    float acc[8] = {0.f, 0.f, 0.f, 0.f, 0.f, 0.f, 0.f, 0.f};
    #pragma unroll 4
    for (int i = lane; i < H_DIM; i += 32) {
        float v = xt[i];
        xh[i] = __float2half_rn(v);
        const float* r = srw + i * 9;
        #pragma unroll
        for (int e = 0; e < 8; e++)
            acc[e] = fmaf(v, r[e], acc[e]);
    }
    #pragma unroll
    for (int e = 0; e < 8; e++)
        #pragma unroll
        for (int o = 16; o; o >>= 1)
            acc[e] += __shfl_xor_sync(0xffffffffu, acc[e], o);

    if (lane == 0) {
        int i0 = 0; float v0 = acc[0];
        #pragma unroll
        for (int j = 1; j < 8; j++) if (acc[j] > v0) { v0 = acc[j]; i0 = j; }
        int i1 = -1; float v1 = -3.4e38f;
        #pragma unroll
        for (int j = 0; j < 8; j++)
            if (j != i0 && acc[j] > v1) { v1 = acc[j]; i1 = j; }
        float p0 = 1.f / (1.f + expf(-v0));
        float p1 = 1.f / (1.f + expf(-v1));
        int pos0 = atomicAdd(&g_counts[i0], 1);
        int pos1 = atomicAdd(&g_counts[i1], 1);
        g_tok[i0 * T_MAX + pos0] = t;
        g_tok[i1 * T_MAX + pos1] = t;
        g_rowgate[i0 * T_MAX + pos0] = p0;
        g_rowgate[i1 * T_MAX + pos1] = p1;
    }
}

// ---------------- weight interleave (R8 version) ----------------
template <bool FIRST>
__global__ void interleave_kernel(const float* __restrict__ w) {
    const int K = FIRST ? H_DIM : F_DIM;
    const int N = FIRST ? F_DIM : H_DIM;
    __half2* wi = (__half2*)(FIRST ? g_w1i : g_w2i);
    int n  = (blockIdx.x * 256 + threadIdx.x) * 4;
    int k2 = blockIdx.y;
    int e  = blockIdx.z;
    size_t eo = (size_t)e * K * N;
    float4 a = *(const float4*)(w + eo + (size_t)(2 * k2)     * N + n);
    float4 b = *(const float4*)(w + eo + (size_t)(2 * k2 + 1) * N + n);
    __half2 o[4];
    o[0] = __halves2half2(__float2half_rn(a.x), __float2half_rn(b.x));
    o[1] = __halves2half2(__float2half_rn(a.y), __float2half_rn(b.y));
    o[2] = __halves2half2(__float2half_rn(a.z), __float2half_rn(b.z));
    o[3] = __halves2half2(__float2half_rn(a.w), __float2half_rn(b.w));
    *(uint4*)(wi + ((size_t)e * (K / 2) + k2) * N + n) = *(const uint4*)o;
}

// ---------------- fp16 mma GEMM (R13 mainloop; GEMM2 epilogue scatters to out) ------
template <bool FIRST>
__global__ __launch_bounds__(256)
void gemm_f16(const float* __restrict__ bias, float* __restrict__ out) {
    const int Kd = FIRST ? H_DIM : F_DIM;
    const int Nd = FIRST ? F_DIM : H_DIM;
    const __half* Ag = FIRST ? g_xh : g_h;
    const __half* Wi = FIRST ? g_w1i : g_w2i;

    int e = blockIdx.z;
    int n_e = g_counts[e];
    int row0 = blockIdx.y * BM;
    if (row0 >= n_e) return;
    int n0 = blockIdx.x * BN;
    int eT = e * T_MAX;

    extern __shared__ __align__(16) char sm[];
    uint32_t sbase = smem_u32(sm);
    int t = threadIdx.x, wid = t >> 5, l = t & 31;
    int q = l & 3, g = l >> 2;

    int ar = t >> 1, hf = t & 1;
    int gr = row0 + ar;
    int grc = (gr < n_e) ? gr : (n_e - 1);
    const __half* a_src;
    if (FIRST) {
        int tok = g_tok[eT + grc];
        a_src = Ag + (size_t)tok * Kd + hf * 16;
    } else {
        a_src = Ag + (size_t)(eT + grc) * Kd + hf * 16;
    }
    uint32_t a_sts = (uint32_t)(ar * APITCH + hf * 32);

    int br = t >> 4, bc = t & 15;
    const __half* b_src = Wi + (((size_t)e * (Kd / 2) + br) * Nd + n0 + bc * 8) * 2;
    uint32_t b_sts = (uint32_t)(ABYTES + br * BPITCH + bc * 32);
    const size_t bstep = (size_t)16 * Nd * 2;

    float c[4][4][4];
    #pragma unroll
    for (int i = 0; i < 4; i++)
        #pragma unroll
        for (int j = 0; j < 4; j++)
            #pragma unroll
            for (int r = 0; r < 4; r++) c[i][j][r] = 0.f;

    auto issue = [&](int it) {
        int s = it % NSTAGE;
        uint32_t ad = sbase + (uint32_t)s * BUFB + a_sts;
        uint32_t bd = sbase + (uint32_t)s * BUFB + b_sts;
        const char* asrc = (const char*)(a_src + (size_t)it * BK);
        const char* bsrc = (const char*)(b_src + (size_t)it * bstep);
        CP16(ad,      asrc);
        CP16(ad + 16, asrc + 16);
        CP16(bd,      bsrc);
        CP16(bd + 16, bsrc + 16);
    };

    int wm = (wid & 1) * 64, wn = (wid >> 1) * 32;
    const int NK = Kd / BK;

    uint32_t a_lm = (uint32_t)((l & 15) * APITCH + (l >> 4) * 16);

    issue(0); CP_COMMIT;
    issue(1); CP_COMMIT;
    issue(2); CP_COMMIT;

    for (int k = 0; k < NK; k++) {
        CP_WAIT2;
        __syncthreads();
        if (k + 3 < NK) issue(k + 3);
        CP_COMMIT;

        uint32_t sAu = sbase + (uint32_t)(k % NSTAGE) * BUFB;
        const char* sB = sm + (k % NSTAGE) * BUFB + ABYTES;

        #pragma unroll
        for (int ks = 0; ks < 2; ks++) {
            uint32_t af[4][4];
            #pragma unroll
            for (int mf = 0; mf < 4; mf++) {
                uint32_t addr = sAu + (uint32_t)((wm + mf * 16) * APITCH + ks * 32) + a_lm;
                LDSM4(af[mf][0], af[mf][1], af[mf][2], af[mf][3], addr);
            }
            #pragma unroll
            for (int nf = 0; nf < 4; nf++) {
                int n_loc = wn + nf * 8 + g;
                uint32_t b0 = *(const uint32_t*)(sB + (ks * 8 + q)     * BPITCH + n_loc * 4);
                uint32_t b1 = *(const uint32_t*)(sB + (ks * 8 + 4 + q) * BPITCH + n_loc * 4);
                #pragma unroll
                for (int mf = 0; mf < 4; mf++)
                    MMA_F16(c[mf][nf], af[mf], b0, b1);
            }
        }
    }

    // -------- epilogue --------
    const float* Bp = bias + (size_t)e * Nd;
    #pragma unroll
    for (int mf = 0; mf < 4; mf++) {
        #pragma unroll
        for (int half = 0; half < 2; half++) {
            int rr = row0 + wm + mf * 16 + g + half * 8;
            if (rr >= n_e) continue;
            if (FIRST) {
                size_t rowoff = (size_t)(eT + rr) * Nd;
                #pragma unroll
                for (int nf = 0; nf < 4; nf++) {
                    int cc = n0 + wn + nf * 8 + q * 2;
                    float v0 = c[mf][nf][half * 2 + 0] + __ldg(Bp + cc);
                    float v1 = c[mf][nf][half * 2 + 1] + __ldg(Bp + cc + 1);
                    v0 = gelu_f(v0);
                    v1 = gelu_f(v1);
                    *(__half2*)(g_h + rowoff + cc) =
                        __halves2half2(__float2half_rn(v0), __float2half_rn(v1));
                }
            } else {
                // fused combine: out[tok] += gate * (acc + bias)
                int   tok  = g_tok[eT + rr];
                float gate = g_rowgate[eT + rr];
                float* orow = out + (size_t)tok * Nd;
                #pragma unroll
                for (int nf = 0; nf < 4; nf++) {
                    int cc = n0 + wn + nf * 8 + q * 2;
                    float v0 = c[mf][nf][half * 2 + 0] + __ldg(Bp + cc);
                    float v1 = c[mf][nf][half * 2 + 1] + __ldg(Bp + cc + 1);
                    atomicAdd(orow + cc,     gate * v0);
                    atomicAdd(orow + cc + 1, gate * v1);
                }
            }
        }
    }
}

// ---------------- launch: forked interleaves, serial G1->G2 (R13 schedule) ---------
extern "C" void kernel_launch(void* const* d_in, const int* in_sizes, int n_in,
                              void* d_out, int out_size) {
    const float* x  = (const float*)d_in[0];
    const float* rw = (const float*)d_in[1];
    const float* w1 = (const float*)d_in[2];
    const float* b1 = (const float*)d_in[3];
    const float* w2 = (const float*)d_in[4];
    const float* b2 = (const float*)d_in[5];
    float* out = (float*)d_out;
    int T = in_sizes[0] / H_DIM;

    static cudaStream_t s1;
    static cudaEvent_t evStart, evI1, evI2;
    static int init = 0;
    if (!init) {
        cudaFuncSetAttribute(gemm_f16<true>,  cudaFuncAttributeMaxDynamicSharedMemorySize, SMEM_DYN);
        cudaFuncSetAttribute(gemm_f16<false>, cudaFuncAttributeMaxDynamicSharedMemorySize, SMEM_DYN);
        cudaStreamCreateWithFlags(&s1, cudaStreamNonBlocking);
        cudaEventCreateWithFlags(&evStart, cudaEventDisableTiming);
        cudaEventCreateWithFlags(&evI1,    cudaEventDisableTiming);
        cudaEventCreateWithFlags(&evI2,    cudaEventDisableTiming);
        init = 1;
    }

    // fork: side stream does the weight interleaves
    cudaEventRecord(evStart, 0);
    cudaStreamWaitEvent(s1, evStart, 0);
    interleave_kernel<true ><<<dim3(F_DIM / 1024, H_DIM / 2, E_NUM), 256, 0, s1>>>(w1);
    cudaEventRecord(evI1, s1);
    interleave_kernel<false><<<dim3(H_DIM / 1024, F_DIM / 2, E_NUM), 256, 0, s1>>>(w2);
    cudaEventRecord(evI2, s1);

    // main stream: zero out, routing (+x2h) in parallel with interleaves
    reset_kernel<<<1, 32>>>();
    zero_out_kernel<<<(T * H_DIM / 4 + 255) / 256, 256>>>(out, T * H_DIM / 4);
    router_kernel<<<(T + 7) / 8, 256>>>(x, rw, T);

    cudaStreamWaitEvent(0, evI1, 0);
    {   // GEMM1: K=H, N=F
        dim3 grid(F_DIM / BN, (T + BM - 1) / BM, E_NUM);
        gemm_f16<true><<<grid, 256, SMEM_DYN>>>(b1, nullptr);
    }
    cudaStreamWaitEvent(0, evI2, 0);
    {   // GEMM2: K=F, N=H, epilogue scatters directly into out
        dim3 grid(H_DIM / BN, (T + BM - 1) / BM, E_NUM);
        gemm_f16<false><<<grid, 256, SMEM_DYN>>>(b2, out);
    }
}

// round 16
// speedup vs baseline: 1.0387x; 1.0098x over previous
#include <cuda_runtime.h>
#include <cuda_fp16.h>
#include <math.h>
#include <stdint.h>

#define H_DIM 1024
#define F_DIM 4096
#define E_NUM 8
#define T_MAX 4096

#define BM 128
#define BN 128
#define BK 32
#define APITCH 80
#define BPITCH 544
#define ABYTES (BM * APITCH)      // 10240
#define BBYTES (16 * BPITCH)      // 8704
#define BUFB   (ABYTES + BBYTES)  // 18944
#define NSTAGE 5
#define SMEM_DYN (NSTAGE * BUFB)  // 94720 -> still 2 CTAs/SM

// ---------------- device scratch (accessed ONLY from device code) ----------------
__device__ int   g_counts[E_NUM];
__device__ int   g_tok[E_NUM * T_MAX];
__device__ float g_gate[T_MAX * 2];
__device__ int   g_slot[T_MAX * 2];
__device__ __align__(16) __half g_xh [(size_t)T_MAX * H_DIM];
__device__ __align__(16) __half g_w1i[(size_t)E_NUM * H_DIM * F_DIM];
__device__ __align__(16) __half g_w2i[(size_t)E_NUM * F_DIM * H_DIM];
__device__ __align__(16) __half g_h  [(size_t)E_NUM * T_MAX * F_DIM];
__device__ __align__(16) float  g_y2 [(size_t)E_NUM * T_MAX * H_DIM];

#define MMA_F16(c, a, b0, b1) \
    asm volatile("mma.sync.aligned.m16n8k16.row.col.f32.f16.f16.f32 " \
        "{%0,%1,%2,%3}, {%4,%5,%6,%7}, {%8,%9}, {%0,%1,%2,%3};" \
        : "+f"((c)[0]),"+f"((c)[1]),"+f"((c)[2]),"+f"((c)[3]) \
        : "r"((a)[0]),"r"((a)[1]),"r"((a)[2]),"r"((a)[3]), "r"(b0),"r"(b1))

#define CP16(d, s) asm volatile("cp.async.cg.shared.global [%0], [%1], 16;" :: "r"(d), "l"(s))
#define CP_COMMIT  asm volatile("cp.async.commit_group;" ::: "memory")
#define CP_WAIT3   asm volatile("cp.async.wait_group 3;" ::: "memory")
#define LDSM4(r0,r1,r2,r3,addr) \
    asm volatile("ldmatrix.sync.aligned.m8n8.x4.shared.b16 {%0,%1,%2,%3}, [%4];" \
        : "=r"(r0),"=r"(r1),"=r"(r2),"=r"(r3) : "r"(addr))

__device__ __forceinline__ uint32_t smem_u32(const void* p) {
    uint32_t a;
    asm("{ .reg .u64 t; cvta.to.shared.u64 t, %1; cvt.u32.u64 %0, t; }" : "=r"(a) : "l"(p));
    return a;
}
__device__ __forceinline__ float gelu_f(float v) {
    return 0.5f * v * (1.0f + erff(v * 0.70710678118654752f));
}

// ---------------- reset ----------------
__global__ void reset_kernel() {
    if (threadIdx.x < E_NUM) g_counts[threadIdx.x] = 0;
}

// ---------------- router: warp-per-token, rw staged in smem (+ fused x->fp16) -------
__global__ __launch_bounds__(256)
void router_kernel(const float* __restrict__ x,
                   const float* __restrict__ rw, int T) {
    __shared__ float srw[H_DIM * 9];
    for (int idx = threadIdx.x; idx < H_DIM * E_NUM; idx += 256)
        srw[(idx >> 3) * 9 + (idx & 7)] = rw[idx];
    __syncthreads();

    int lane = threadIdx.x & 31;
    int t = blockIdx.x * 8 + (threadIdx.x >> 5);
    if (t >= T) return;
    const float* xt = x + (size_t)t * H_DIM;
    __half* xh = g_xh + (size_t)t * H_DIM;

    float acc[8] = {0.f, 0.f, 0.f, 0.f, 0.f, 0.f, 0.f, 0.f};
    #pragma unroll 4
    for (int i = lane; i < H_DIM; i += 32) {
        float v = xt[i];
        xh[i] = __float2half_rn(v);
        const float* r = srw + i * 9;
        #pragma unroll
        for (int e = 0; e < 8; e++)
            acc[e] = fmaf(v, r[e], acc[e]);
    }
    #pragma unroll
    for (int e = 0; e < 8; e++)
        #pragma unroll
        for (int o = 16; o; o >>= 1)
            acc[e] += __shfl_xor_sync(0xffffffffu, acc[e], o);

    if (lane == 0) {
        int i0 = 0; float v0 = acc[0];
        #pragma unroll
        for (int j = 1; j < 8; j++) if (acc[j] > v0) { v0 = acc[j]; i0 = j; }
        int i1 = -1; float v1 = -3.4e38f;
        #pragma unroll
        for (int j = 0; j < 8; j++)
            if (j != i0 && acc[j] > v1) { v1 = acc[j]; i1 = j; }
        float p0 = 1.f / (1.f + expf(-v0));
        float p1 = 1.f / (1.f + expf(-v1));
        int pos0 = atomicAdd(&g_counts[i0], 1);
        int pos1 = atomicAdd(&g_counts[i1], 1);
        g_tok[i0 * T_MAX + pos0] = t;
        g_tok[i1 * T_MAX + pos1] = t;
        g_gate[t * 2 + 0] = p0;  g_slot[t * 2 + 0] = i0 * T_MAX + pos0;
        g_gate[t * 2 + 1] = p1;  g_slot[t * 2 + 1] = i1 * T_MAX + pos1;
    }
}

// ---------------- weight interleave (R8 version) ----------------
template <bool FIRST>
__global__ void interleave_kernel(const float* __restrict__ w) {
    const int K = FIRST ? H_DIM : F_DIM;
    const int N = FIRST ? F_DIM : H_DIM;
    __half2* wi = (__half2*)(FIRST ? g_w1i : g_w2i);
    int n  = (blockIdx.x * 256 + threadIdx.x) * 4;
    int k2 = blockIdx.y;
    int e  = blockIdx.z;
    size_t eo = (size_t)e * K * N;
    float4 a = *(const float4*)(w + eo + (size_t)(2 * k2)     * N + n);
    float4 b = *(const float4*)(w + eo + (size_t)(2 * k2 + 1) * N + n);
    __half2 o[4];
    o[0] = __halves2half2(__float2half_rn(a.x), __float2half_rn(b.x));
    o[1] = __halves2half2(__float2half_rn(a.y), __float2half_rn(b.y));
    o[2] = __halves2half2(__float2half_rn(a.z), __float2half_rn(b.z));
    o[3] = __halves2half2(__float2half_rn(a.w), __float2half_rn(b.w));
    *(uint4*)(wi + ((size_t)e * (K / 2) + k2) * N + n) = *(const uint4*)o;
}

// ---------------- fp16 mma GEMM (R13 mainloop, 5-stage pipeline) --------------------
template <bool FIRST>
__global__ __launch_bounds__(256)
void gemm_f16(const float* __restrict__ bias) {
    const int Kd = FIRST ? H_DIM : F_DIM;
    const int Nd = FIRST ? F_DIM : H_DIM;
    const __half* Ag = FIRST ? g_xh : g_h;
    const __half* Wi = FIRST ? g_w1i : g_w2i;

    int e = blockIdx.z;
    int n_e = g_counts[e];
    int row0 = blockIdx.y * BM;
    if (row0 >= n_e) return;
    int n0 = blockIdx.x * BN;
    int eT = e * T_MAX;

    extern __shared__ __align__(16) char sm[];
    uint32_t sbase = smem_u32(sm);
    int t = threadIdx.x, wid = t >> 5, l = t & 31;
    int q = l & 3, g = l >> 2;

    int ar = t >> 1, hf = t & 1;
    int gr = row0 + ar;
    int grc = (gr < n_e) ? gr : (n_e - 1);       // clamp: never stored for rr>=n_e
    const __half* a_src;
    if (FIRST) {
        int tok = g_tok[eT + grc];
        a_src = Ag + (size_t)tok * Kd + hf * 16;
    } else {
        a_src = Ag + (size_t)(eT + grc) * Kd + hf * 16;
    }
    uint32_t a_sts = (uint32_t)(ar * APITCH + hf * 32);

    int br = t >> 4, bc = t & 15;
    const __half* b_src = Wi + (((size_t)e * (Kd / 2) + br) * Nd + n0 + bc * 8) * 2;
    uint32_t b_sts = (uint32_t)(ABYTES + br * BPITCH + bc * 32);
    const size_t bstep = (size_t)16 * Nd * 2;

    float c[4][4][4];
    #pragma unroll
    for (int i = 0; i < 4; i++)
        #pragma unroll
        for (int j = 0; j < 4; j++)
            #pragma unroll
            for (int r = 0; r < 4; r++) c[i][j][r] = 0.f;

    auto issue = [&](int it) {
        int s = it % NSTAGE;
        uint32_t ad = sbase + (uint32_t)s * BUFB + a_sts;
        uint32_t bd = sbase + (uint32_t)s * BUFB + b_sts;
        const char* asrc = (const char*)(a_src + (size_t)it * BK);
        const char* bsrc = (const char*)(b_src + (size_t)it * bstep);
        CP16(ad,      asrc);
        CP16(ad + 16, asrc + 16);
        CP16(bd,      bsrc);
        CP16(bd + 16, bsrc + 16);
    };

    int wm = (wid & 1) * 64, wn = (wid >> 1) * 32;
    const int NK = Kd / BK;

    uint32_t a_lm = (uint32_t)((l & 15) * APITCH + (l >> 4) * 16);

    issue(0); CP_COMMIT;
    issue(1); CP_COMMIT;
    issue(2); CP_COMMIT;
    issue(3); CP_COMMIT;

    for (int k = 0; k < NK; k++) {
        CP_WAIT3;
        __syncthreads();
        if (k + 4 < NK) issue(k + 4);
        CP_COMMIT;

        uint32_t sAu = sbase + (uint32_t)(k % NSTAGE) * BUFB;
        const char* sB = sm + (k % NSTAGE) * BUFB + ABYTES;

        #pragma unroll
        for (int ks = 0; ks < 2; ks++) {
            uint32_t af[4][4];
            #pragma unroll
            for (int mf = 0; mf < 4; mf++) {
                uint32_t addr = sAu + (uint32_t)((wm + mf * 16) * APITCH + ks * 32) + a_lm;
                LDSM4(af[mf][0], af[mf][1], af[mf][2], af[mf][3], addr);
            }
            #pragma unroll
            for (int nf = 0; nf < 4; nf++) {
                int n_loc = wn + nf * 8 + g;
                uint32_t b0 = *(const uint32_t*)(sB + (ks * 8 + q)     * BPITCH + n_loc * 4);
                uint32_t b1 = *(const uint32_t*)(sB + (ks * 8 + 4 + q) * BPITCH + n_loc * 4);
                #pragma unroll
                for (int mf = 0; mf < 4; mf++)
                    MMA_F16(c[mf][nf], af[mf], b0, b1);
            }
        }
    }

    // -------- epilogue --------
    const float* Bp = bias + (size_t)e * Nd;
    #pragma unroll
    for (int mf = 0; mf < 4; mf++) {
        #pragma unroll
        for (int half = 0; half < 2; half++) {
            int rr = row0 + wm + mf * 16 + g + half * 8;
            if (rr >= n_e) continue;
            size_t rowoff = (size_t)(eT + rr) * Nd;
            #pragma unroll
            for (int nf = 0; nf < 4; nf++) {
                int cc = n0 + wn + nf * 8 + q * 2;
                float v0 = c[mf][nf][half * 2 + 0] + __ldg(Bp + cc);
                float v1 = c[mf][nf][half * 2 + 1] + __ldg(Bp + cc + 1);
                if (FIRST) {
                    v0 = gelu_f(v0);
                    v1 = gelu_f(v1);
                    *(__half2*)(g_h + rowoff + cc) =
                        __halves2half2(__float2half_rn(v0), __float2half_rn(v1));
                } else {
                    *(float2*)(g_y2 + rowoff + cc) = make_float2(v0, v1);
                }
            }
        }
    }
}

// ---------------- combine ----------------
__global__ void combine_kernel(float* __restrict__ out, int T) {
    int idx = blockIdx.x * blockDim.x + threadIdx.x;
    int total = T * (H_DIM / 4);
    if (idx >= total) return;
    int t = idx / (H_DIM / 4);
    int j = (idx % (H_DIM / 4)) * 4;
    float g0 = g_gate[t * 2 + 0], g1 = g_gate[t * 2 + 1];
    int   s0 = g_slot[t * 2 + 0], s1 = g_slot[t * 2 + 1];
    float4 a = *(const float4*)&g_y2[(size_t)s0 * H_DIM + j];
    float4 b = *(const float4*)&g_y2[(size_t)s1 * H_DIM + j];
    float4 o;
    o.x = fmaf(g0, a.x, g1 * b.x);
    o.y = fmaf(g0, a.y, g1 * b.y);
    o.z = fmaf(g0, a.z, g1 * b.z);
    o.w = fmaf(g0, a.w, g1 * b.w);
    *(float4*)(out + (size_t)t * H_DIM + j) = o;
}

// ---------------- launch: fork interleaves onto a side stream (R13 schedule) --------
extern "C" void kernel_launch(void* const* d_in, const int* in_sizes, int n_in,
                              void* d_out, int out_size) {
    const float* x  = (const float*)d_in[0];
    const float* rw = (const float*)d_in[1];
    const float* w1 = (const float*)d_in[2];
    const float* b1 = (const float*)d_in[3];
    const float* w2 = (const float*)d_in[4];
    const float* b2 = (const float*)d_in[5];
    float* out = (float*)d_out;
    int T = in_sizes[0] / H_DIM;

    static cudaStream_t s1;
    static cudaEvent_t evStart, evI1, evI2;
    static int init = 0;
    if (!init) {
        cudaFuncSetAttribute(gemm_f16<true>,  cudaFuncAttributeMaxDynamicSharedMemorySize, SMEM_DYN);
        cudaFuncSetAttribute(gemm_f16<false>, cudaFuncAttributeMaxDynamicSharedMemorySize, SMEM_DYN);
        cudaStreamCreateWithFlags(&s1, cudaStreamNonBlocking);
        cudaEventCreateWithFlags(&evStart, cudaEventDisableTiming);
        cudaEventCreateWithFlags(&evI1,    cudaEventDisableTiming);
        cudaEventCreateWithFlags(&evI2,    cudaEventDisableTiming);
        init = 1;
    }

    // fork: side stream does the weight interleaves
    cudaEventRecord(evStart, 0);
    cudaStreamWaitEvent(s1, evStart, 0);
    interleave_kernel<true ><<<dim3(F_DIM / 1024, H_DIM / 2, E_NUM), 256, 0, s1>>>(w1);
    cudaEventRecord(evI1, s1);
    interleave_kernel<false><<<dim3(H_DIM / 1024, F_DIM / 2, E_NUM), 256, 0, s1>>>(w2);
    cudaEventRecord(evI2, s1);

    // main stream: routing (+x2h) in parallel with interleaves
    reset_kernel<<<1, 32>>>();
    router_kernel<<<(T + 7) / 8, 256>>>(x, rw, T);

    cudaStreamWaitEvent(0, evI1, 0);
    {   // GEMM1: K=H, N=F
        dim3 grid(F_DIM / BN, (T + BM - 1) / BM, E_NUM);
        gemm_f16<true><<<grid, 256, SMEM_DYN>>>(b1);
    }
    cudaStreamWaitEvent(0, evI2, 0);
    {   // GEMM2: K=F, N=H
        dim3 grid(H_DIM / BN, (T + BM - 1) / BM, E_NUM);
        gemm_f16<false><<<grid, 256, SMEM_DYN>>>(b2);
    }

    int total = T * (H_DIM / 4);
    combine_kernel<<<(total + 255) / 256, 256>>>(out, T);
}

// round 17
// speedup vs baseline: 1.0536x; 1.0143x over previous
#include <cuda_runtime.h>
#include <cuda_fp16.h>
#include <math.h>
#include <stdint.h>

#define H_DIM 1024
#define F_DIM 4096
#define E_NUM 8
#define T_MAX 4096

#define BM 128
#define BN 128
#define BK 32
#define APITCH 80
#define BPITCH 544
#define ABYTES (BM * APITCH)      // 10240
#define BBYTES (16 * BPITCH)      // 8704
#define BUFB   (ABYTES + BBYTES)  // 18944
#define NSTAGE 4
#define SMEM_DYN (NSTAGE * BUFB)  // 75776

// ---------------- device scratch (accessed ONLY from device code, except
// g_counts whose ADDRESS is resolved via cudaGetSymbolAddress for memset) -----------
__device__ int   g_counts[E_NUM];
__device__ int   g_tok[E_NUM * T_MAX];
__device__ float g_gate[T_MAX * 2];
__device__ int   g_slot[T_MAX * 2];
__device__ __align__(16) __half g_xh [(size_t)T_MAX * H_DIM];
__device__ __align__(16) __half g_w1i[(size_t)E_NUM * H_DIM * F_DIM];
__device__ __align__(16) __half g_w2i[(size_t)E_NUM * F_DIM * H_DIM];
__device__ __align__(16) __half g_h  [(size_t)E_NUM * T_MAX * F_DIM];
__device__ __align__(16) float  g_y2 [(size_t)E_NUM * T_MAX * H_DIM];

#define MMA_F16(c, a, b0, b1) \
    asm volatile("mma.sync.aligned.m16n8k16.row.col.f32.f16.f16.f32 " \
        "{%0,%1,%2,%3}, {%4,%5,%6,%7}, {%8,%9}, {%0,%1,%2,%3};" \
        : "+f"((c)[0]),"+f"((c)[1]),"+f"((c)[2]),"+f"((c)[3]) \
        : "r"((a)[0]),"r"((a)[1]),"r"((a)[2]),"r"((a)[3]), "r"(b0),"r"(b1))

#define CP16(d, s) asm volatile("cp.async.cg.shared.global [%0], [%1], 16;" :: "r"(d), "l"(s))
#define CP_COMMIT  asm volatile("cp.async.commit_group;" ::: "memory")
#define CP_WAIT2   asm volatile("cp.async.wait_group 2;" ::: "memory")
#define LDSM4(r0,r1,r2,r3,addr) \
    asm volatile("ldmatrix.sync.aligned.m8n8.x4.shared.b16 {%0,%1,%2,%3}, [%4];" \
        : "=r"(r0),"=r"(r1),"=r"(r2),"=r"(r3) : "r"(addr))

__device__ __forceinline__ uint32_t smem_u32(const void* p) {
    uint32_t a;
    asm("{ .reg .u64 t; cvta.to.shared.u64 t, %1; cvt.u32.u64 %0, t; }" : "=r"(a) : "l"(p));
    return a;
}
__device__ __forceinline__ float gelu_f(float v) {
    return 0.5f * v * (1.0f + erff(v * 0.70710678118654752f));
}

// ---------------- router: warp-per-token, rw staged in smem (+ fused x->fp16) -------
__global__ __launch_bounds__(256)
void router_kernel(const float* __restrict__ x,
                   const float* __restrict__ rw, int T) {
    __shared__ float srw[H_DIM * 9];
    for (int idx = threadIdx.x; idx < H_DIM * E_NUM; idx += 256)
        srw[(idx >> 3) * 9 + (idx & 7)] = rw[idx];
    __syncthreads();

    int lane = threadIdx.x & 31;
    int t = blockIdx.x * 8 + (threadIdx.x >> 5);
    if (t >= T) return;
    const float* xt = x + (size_t)t * H_DIM;
    __half* xh = g_xh + (size_t)t * H_DIM;

    float acc[8] = {0.f, 0.f, 0.f, 0.f, 0.f, 0.f, 0.f, 0.f};
    #pragma unroll 4
    for (int i = lane; i < H_DIM; i += 32) {
        float v = xt[i];
        xh[i] = __float2half_rn(v);
        const float* r = srw + i * 9;
        #pragma unroll
        for (int e = 0; e < 8; e++)
            acc[e] = fmaf(v, r[e], acc[e]);
    }
    #pragma unroll
    for (int e = 0; e < 8; e++)
        #pragma unroll
        for (int o = 16; o; o >>= 1)
            acc[e] += __shfl_xor_sync(0xffffffffu, acc[e], o);

    if (lane == 0) {
        int i0 = 0; float v0 = acc[0];
        #pragma unroll
        for (int j = 1; j < 8; j++) if (acc[j] > v0) { v0 = acc[j]; i0 = j; }
        int i1 = -1; float v1 = -3.4e38f;
        #pragma unroll
        for (int j = 0; j < 8; j++)
            if (j != i0 && acc[j] > v1) { v1 = acc[j]; i1 = j; }
        float p0 = 1.f / (1.f + expf(-v0));
        float p1 = 1.f / (1.f + expf(-v1));
        int pos0 = atomicAdd(&g_counts[i0], 1);
        int pos1 = atomicAdd(&g_counts[i1], 1);
        g_tok[i0 * T_MAX + pos0] = t;
        g_tok[i1 * T_MAX + pos1] = t;
        g_gate[t * 2 + 0] = p0;  g_slot[t * 2 + 0] = i0 * T_MAX + pos0;
        g_gate[t * 2 + 1] = p1;  g_slot[t * 2 + 1] = i1 * T_MAX + pos1;
    }
}

// ---------------- weight interleave (R8 version) ----------------
template <bool FIRST>
__global__ void interleave_kernel(const float* __restrict__ w) {
    const int K = FIRST ? H_DIM : F_DIM;
    const int N = FIRST ? F_DIM : H_DIM;
    __half2* wi = (__half2*)(FIRST ? g_w1i : g_w2i);
    int n  = (blockIdx.x * 256 + threadIdx.x) * 4;
    int k2 = blockIdx.y;
    int e  = blockIdx.z;
    size_t eo = (size_t)e * K * N;
    float4 a = *(const float4*)(w + eo + (size_t)(2 * k2)     * N + n);
    float4 b = *(const float4*)(w + eo + (size_t)(2 * k2 + 1) * N + n);
    __half2 o[4];
    o[0] = __halves2half2(__float2half_rn(a.x), __float2half_rn(b.x));
    o[1] = __halves2half2(__float2half_rn(a.y), __float2half_rn(b.y));
    o[2] = __halves2half2(__float2half_rn(a.z), __float2half_rn(b.z));
    o[3] = __halves2half2(__float2half_rn(a.w), __float2half_rn(b.w));
    *(uint4*)(wi + ((size_t)e * (K / 2) + k2) * N + n) = *(const uint4*)o;
}

// ---------------- fp16 mma GEMM (R13: BM=128, cp.async 4-stage, ldmatrix A) ---------
template <bool FIRST>
__global__ __launch_bounds__(256)
void gemm_f16(const float* __restrict__ bias) {
    const int Kd = FIRST ? H_DIM : F_DIM;
    const int Nd = FIRST ? F_DIM : H_DIM;
    const __half* Ag = FIRST ? g_xh : g_h;
    const __half* Wi = FIRST ? g_w1i : g_w2i;

    int e = blockIdx.z;
    int n_e = g_counts[e];
    int row0 = blockIdx.y * BM;
    if (row0 >= n_e) return;
    int n0 = blockIdx.x * BN;
    int eT = e * T_MAX;

    extern __shared__ __align__(16) char sm[];
    uint32_t sbase = smem_u32(sm);
    int t = threadIdx.x, wid = t >> 5, l = t & 31;
    int q = l & 3, g = l >> 2;

    int ar = t >> 1, hf = t & 1;
    int gr = row0 + ar;
    int grc = (gr < n_e) ? gr : (n_e - 1);       // clamp: never stored for rr>=n_e
    const __half* a_src;
    if (FIRST) {
        int tok = g_tok[eT + grc];
        a_src = Ag + (size_t)tok * Kd + hf * 16;
    } else {
        a_src = Ag + (size_t)(eT + grc) * Kd + hf * 16;
    }
    uint32_t a_sts = (uint32_t)(ar * APITCH + hf * 32);

    int br = t >> 4, bc = t & 15;
    const __half* b_src = Wi + (((size_t)e * (Kd / 2) + br) * Nd + n0 + bc * 8) * 2;
    uint32_t b_sts = (uint32_t)(ABYTES + br * BPITCH + bc * 32);
    const size_t bstep = (size_t)16 * Nd * 2;

    float c[4][4][4];
    #pragma unroll
    for (int i = 0; i < 4; i++)
        #pragma unroll
        for (int j = 0; j < 4; j++)
            #pragma unroll
            for (int r = 0; r < 4; r++) c[i][j][r] = 0.f;

    auto issue = [&](int it) {
        int s = it % NSTAGE;
        uint32_t ad = sbase + (uint32_t)s * BUFB + a_sts;
        uint32_t bd = sbase + (uint32_t)s * BUFB + b_sts;
        const char* asrc = (const char*)(a_src + (size_t)it * BK);
        const char* bsrc = (const char*)(b_src + (size_t)it * bstep);
        CP16(ad,      asrc);
        CP16(ad + 16, asrc + 16);
        CP16(bd,      bsrc);
        CP16(bd + 16, bsrc + 16);
    };

    int wm = (wid & 1) * 64, wn = (wid >> 1) * 32;
    const int NK = Kd / BK;

    uint32_t a_lm = (uint32_t)((l & 15) * APITCH + (l >> 4) * 16);

    issue(0); CP_COMMIT;
    issue(1); CP_COMMIT;
    issue(2); CP_COMMIT;

    for (int k = 0; k < NK; k++) {
        CP_WAIT2;
        __syncthreads();
        if (k + 3 < NK) issue(k + 3);
        CP_COMMIT;

        uint32_t sAu = sbase + (uint32_t)(k % NSTAGE) * BUFB;
        const char* sB = sm + (k % NSTAGE) * BUFB + ABYTES;

        #pragma unroll
        for (int ks = 0; ks < 2; ks++) {
            uint32_t af[4][4];
            #pragma unroll
            for (int mf = 0; mf < 4; mf++) {
                uint32_t addr = sAu + (uint32_t)((wm + mf * 16) * APITCH + ks * 32) + a_lm;
                LDSM4(af[mf][0], af[mf][1], af[mf][2], af[mf][3], addr);
            }
            #pragma unroll
            for (int nf = 0; nf < 4; nf++) {
                int n_loc = wn + nf * 8 + g;
                uint32_t b0 = *(const uint32_t*)(sB + (ks * 8 + q)     * BPITCH + n_loc * 4);
                uint32_t b1 = *(const uint32_t*)(sB + (ks * 8 + 4 + q) * BPITCH + n_loc * 4);
                #pragma unroll
                for (int mf = 0; mf < 4; mf++)
                    MMA_F16(c[mf][nf], af[mf], b0, b1);
            }
        }
    }

    // -------- epilogue --------
    const float* Bp = bias + (size_t)e * Nd;
    #pragma unroll
    for (int mf = 0; mf < 4; mf++) {
        #pragma unroll
        for (int half = 0; half < 2; half++) {
            int rr = row0 + wm + mf * 16 + g + half * 8;
            if (rr >= n_e) continue;
            size_t rowoff = (size_t)(eT + rr) * Nd;
            #pragma unroll
            for (int nf = 0; nf < 4; nf++) {
                int cc = n0 + wn + nf * 8 + q * 2;
                float v0 = c[mf][nf][half * 2 + 0] + __ldg(Bp + cc);
                float v1 = c[mf][nf][half * 2 + 1] + __ldg(Bp + cc + 1);
                if (FIRST) {
                    v0 = gelu_f(v0);
                    v1 = gelu_f(v1);
                    *(__half2*)(g_h + rowoff + cc) =
                        __halves2half2(__float2half_rn(v0), __float2half_rn(v1));
                } else {
                    *(float2*)(g_y2 + rowoff + cc) = make_float2(v0, v1);
                }
            }
        }
    }
}

// ---------------- combine ----------------
__global__ void combine_kernel(float* __restrict__ out, int T) {
    int idx = blockIdx.x * blockDim.x + threadIdx.x;
    int total = T * (H_DIM / 4);
    if (idx >= total) return;
    int t = idx / (H_DIM / 4);
    int j = (idx % (H_DIM / 4)) * 4;
    float g0 = g_gate[t * 2 + 0], g1 = g_gate[t * 2 + 1];
    int   s0 = g_slot[t * 2 + 0], s1 = g_slot[t * 2 + 1];
    float4 a = *(const float4*)&g_y2[(size_t)s0 * H_DIM + j];
    float4 b = *(const float4*)&g_y2[(size_t)s1 * H_DIM + j];
    float4 o;
    o.x = fmaf(g0, a.x, g1 * b.x);
    o.y = fmaf(g0, a.y, g1 * b.y);
    o.z = fmaf(g0, a.z, g1 * b.z);
    o.w = fmaf(g0, a.w, g1 * b.w);
    *(float4*)(out + (size_t)t * H_DIM + j) = o;
}

// ---------------- launch: R13 schedule; reset via memset node -----------------------
extern "C" void kernel_launch(void* const* d_in, const int* in_sizes, int n_in,
                              void* d_out, int out_size) {
    const float* x  = (const float*)d_in[0];
    const float* rw = (const float*)d_in[1];
    const float* w1 = (const float*)d_in[2];
    const float* b1 = (const float*)d_in[3];
    const float* w2 = (const float*)d_in[4];
    const float* b2 = (const float*)d_in[5];
    float* out = (float*)d_out;
    int T = in_sizes[0] / H_DIM;

    static cudaStream_t s1;
    static cudaEvent_t evStart, evI1, evI2;
    static void* counts_ptr = nullptr;
    static int init = 0;
    if (!init) {
        cudaFuncSetAttribute(gemm_f16<true>,  cudaFuncAttributeMaxDynamicSharedMemorySize, SMEM_DYN);
        cudaFuncSetAttribute(gemm_f16<false>, cudaFuncAttributeMaxDynamicSharedMemorySize, SMEM_DYN);
        cudaStreamCreateWithFlags(&s1, cudaStreamNonBlocking);
        cudaEventCreateWithFlags(&evStart, cudaEventDisableTiming);
        cudaEventCreateWithFlags(&evI1,    cudaEventDisableTiming);
        cudaEventCreateWithFlags(&evI2,    cudaEventDisableTiming);
        cudaGetSymbolAddress(&counts_ptr, g_counts);
        init = 1;
    }

    // fork: side stream does the weight interleaves
    cudaEventRecord(evStart, 0);
    cudaStreamWaitEvent(s1, evStart, 0);
    interleave_kernel<true ><<<dim3(F_DIM / 1024, H_DIM / 2, E_NUM), 256, 0, s1>>>(w1);
    cudaEventRecord(evI1, s1);
    interleave_kernel<false><<<dim3(H_DIM / 1024, F_DIM / 2, E_NUM), 256, 0, s1>>>(w2);
    cudaEventRecord(evI2, s1);

    // main stream: zero counts (memset node), routing (+x2h) in parallel with interleaves
    cudaMemsetAsync(counts_ptr, 0, E_NUM * sizeof(int), 0);
    router_kernel<<<(T + 7) / 8, 256>>>(x, rw, T);

    cudaStreamWaitEvent(0, evI1, 0);
    {   // GEMM1: K=H, N=F
        dim3 grid(F_DIM / BN, (T + BM - 1) / BM, E_NUM);
        gemm_f16<true><<<grid, 256, SMEM_DYN>>>(b1);
    }
    cudaStreamWaitEvent(0, evI2, 0);
    {   // GEMM2: K=F, N=H
        dim3 grid(H_DIM / BN, (T + BM - 1) / BM, E_NUM);
        gemm_f16<false><<<grid, 256, SMEM_DYN>>>(b2);
    }

    int total = T * (H_DIM / 4);
    combine_kernel<<<(total + 255) / 256, 256>>>(out, T);
}